// round 7
// baseline (speedup 1.0000x reference)
#include <cuda_runtime.h>
#include <cuda_bf16.h>

// SGConv: out = (D^-1/2 A D^-1/2)^2 * feat @ W + b
// N=100000 nodes, 64 features, E=1000000 edges.
//
// Memory-guard constraints (R1/R3): big __device__ segments trigger a fixed
// 128MiB driver arena inside the checkpoint window; pre-main CUDA calls break
// harness handles (R2). => globals ~5.6MB; h1 lives in d_out; h2 lives in
// shared memory of the persistent fused kernel.
//
// R7 = R6 resubmit (R6 died to broker-level container failure, same as R4
// which passed on resubmit): k_fused 1024 threads, 4x-unrolled MLP gathers,
// norm fused into scan1. Hardening: grid-barrier spin is BOUNDED so any
// residency-invariant violation yields a fast wrong answer (diagnosable)
// instead of a container-killing hang.

#define MAXN 100000
#define MAXE 1000000
#define F 64
#define SCAN_BLK 1024
#define ROWS_PB_CAP 800   // smem: 800*65*4 + 16KB < 227KB opt-in limit

__device__ int   g_deg[MAXN];
__device__ int   g_cur[MAXN];
__device__ int   g_rowptr[MAXN + 1];
__device__ int   g_chunksum[128];
__device__ int   g_chunkoff[128];
__device__ float g_norm[MAXN];
__device__ int   g_csr_src[MAXE];
__device__ int   g_bar;

// ---------------------------------------------------------------- zero
__global__ void k_zero(int N) {
    int i = blockIdx.x * blockDim.x + threadIdx.x;
    if (i < N) { g_deg[i] = 0; g_cur[i] = 0; }
    if (i == 0) g_bar = 0;
}

// ---------------------------------------------------------------- histogram
__global__ void k_hist(const int* __restrict__ dst, int E) {
    int e = blockIdx.x * blockDim.x + threadIdx.x;
    if (e < E) atomicAdd(&g_deg[dst[e]], 1);
}

// ---------------------------------------------------------------- scan (+norm fused)
__global__ void k_scan1(int N) {
    __shared__ int sh[SCAN_BLK];
    int t = threadIdx.x;
    int i = blockIdx.x * SCAN_BLK + t;
    int v = (i < N) ? g_deg[i] : 0;
    if (i < N) g_norm[i] = rsqrtf(fmaxf((float)v, 1.0f));   // fused norm
    sh[t] = v;
    __syncthreads();
    #pragma unroll
    for (int off = 1; off < SCAN_BLK; off <<= 1) {
        int x = (t >= off) ? sh[t - off] : 0;
        __syncthreads();
        sh[t] += x;
        __syncthreads();
    }
    if (i < N) g_rowptr[i] = sh[t] - v;          // exclusive (partial)
    if (t == SCAN_BLK - 1) g_chunksum[blockIdx.x] = sh[t];
}

__global__ void k_scan2(int nblocks) {
    if (threadIdx.x == 0 && blockIdx.x == 0) {
        int run = 0;
        for (int b = 0; b < nblocks; b++) {
            g_chunkoff[b] = run;
            run += g_chunksum[b];
        }
    }
}

__global__ void k_scan3(int N, int E) {
    int i = blockIdx.x * blockDim.x + threadIdx.x;
    if (i < N) g_rowptr[i] += g_chunkoff[i / SCAN_BLK];
    if (i == 0) g_rowptr[N] = E;
}

// ---------------------------------------------------------------- CSR fill
__global__ void k_fill(const int* __restrict__ src, const int* __restrict__ dst, int E) {
    int e = blockIdx.x * blockDim.x + threadIdx.x;
    if (e < E) {
        int d = dst[e];
        int p = g_rowptr[d] + atomicAdd(&g_cur[d], 1);
        g_csr_src[p] = src[e];
    }
}

// ---------------------------------------------------------------- gather core
// one warp gathers one dst row; lane owns float2. 4x unrolled: 4 independent
// index loads batched first, then 8 independent dependent loads -> MLP 4-8.
__device__ __forceinline__ float2 gather_row(const float2* __restrict__ xr,
                                             int beg, int end, float nd, int lane) {
    float2 a0 = make_float2(0.f, 0.f), a1 = make_float2(0.f, 0.f);
    float2 a2 = make_float2(0.f, 0.f), a3 = make_float2(0.f, 0.f);
    int j = beg;
    for (; j + 3 < end; j += 4) {
        int s0 = __ldg(&g_csr_src[j]);
        int s1 = __ldg(&g_csr_src[j + 1]);
        int s2 = __ldg(&g_csr_src[j + 2]);
        int s3 = __ldg(&g_csr_src[j + 3]);
        float w0 = __ldg(&g_norm[s0]);
        float w1 = __ldg(&g_norm[s1]);
        float w2 = __ldg(&g_norm[s2]);
        float w3 = __ldg(&g_norm[s3]);
        float2 v0 = xr[s0 * 32 + lane];
        float2 v1 = xr[s1 * 32 + lane];
        float2 v2 = xr[s2 * 32 + lane];
        float2 v3 = xr[s3 * 32 + lane];
        a0.x += w0 * v0.x; a0.y += w0 * v0.y;
        a1.x += w1 * v1.x; a1.y += w1 * v1.y;
        a2.x += w2 * v2.x; a2.y += w2 * v2.y;
        a3.x += w3 * v3.x; a3.y += w3 * v3.y;
    }
    for (; j < end; j++) {
        int s = __ldg(&g_csr_src[j]);
        float w = __ldg(&g_norm[s]);
        float2 v = xr[s * 32 + lane];
        a0.x += w * v.x; a0.y += w * v.y;
    }
    float2 acc;
    acc.x = nd * ((a0.x + a1.x) + (a2.x + a3.x));
    acc.y = nd * ((a0.y + a1.y) + (a2.y + a3.y));
    return acc;
}

// ---------------------------------------------------------------- hop1
__global__ void k_hop1(const float* __restrict__ x, float* __restrict__ y, int N) {
    int warp = (blockIdx.x * blockDim.x + threadIdx.x) >> 5;
    int lane = threadIdx.x & 31;
    if (warp >= N) return;
    int beg = g_rowptr[warp];
    int end = g_rowptr[warp + 1];
    float nd = g_norm[warp];
    float2 acc = gather_row((const float2*)x, beg, end, nd, lane);
    ((float2*)y)[warp * 32 + lane] = acc;
}

// ---------------------------------------------------------------- fused hop2 + GEMM
// nblocks <= #SMs, big dyn smem forces 1 block/SM -> all blocks resident ->
// grid barrier safe. 1024 threads: 32 gather warps, 2x GEMM issue vs 512.
// smem: h2[rows_pb][65] (padded) then W[64][64]. x and out ALIAS (= d_out);
// phases separated by the grid barrier.
__global__ void __launch_bounds__(1024, 1)
k_fused(const float* x, float* out, const float* __restrict__ Wm,
        const float* __restrict__ bias, int N, int rows_pb, int nblocks) {
    extern __shared__ float sm[];
    float* h2 = sm;                       // rows_pb * 65
    float* Ws = sm + rows_pb * 65;        // 64*64

    int tid  = threadIdx.x;
    int wid  = tid >> 5;
    int lane = tid & 31;
    int row0 = blockIdx.x * rows_pb;

    for (int i = tid; i < F * F; i += blockDim.x) Ws[i] = Wm[i];

    // ---- phase 1: gather h2 rows into smem (reads x = d_out anywhere)
    const float2* xr = (const float2*)x;
    for (int lr = wid; lr < rows_pb; lr += 32) {
        int r = row0 + lr;
        float2 acc = make_float2(0.f, 0.f);
        if (r < N) {
            acc = gather_row(xr, g_rowptr[r], g_rowptr[r + 1], g_norm[r], lane);
        }
        h2[lr * 65 + 2 * lane]     = acc.x;
        h2[lr * 65 + 2 * lane + 1] = acc.y;
    }

    // ---- software grid barrier (all nblocks co-resident by construction).
    // BOUNDED spin: unreachable bound in correct operation; guarantees the
    // kernel can never hang the harness if an invariant is ever violated.
    __syncthreads();
    __threadfence();
    if (tid == 0) {
        atomicAdd(&g_bar, 1);
        long long guard = 0;
        while (*(volatile int*)&g_bar < nblocks && guard < (160LL << 20)) {
            __nanosleep(64);
            guard++;
        }
    }
    __syncthreads();
    __threadfence();

    // ---- phase 2: out rows = h2 @ W + b, 256-row tiles, 4x4 per thread
    int tx = tid & 15;          // 16 col groups * 4 cols = 64
    int ty = tid >> 4;          // 64 row groups * 4 rows = 256 rows/tile
    int c0 = tx * 4;
    float4 bv = *(const float4*)&bias[c0];

    for (int t0 = 0; t0 < rows_pb; t0 += 256) {
        float acc[4][4];
        #pragma unroll
        for (int i = 0; i < 4; i++) {
            acc[i][0] = bv.x; acc[i][1] = bv.y; acc[i][2] = bv.z; acc[i][3] = bv.w;
        }
        int rbase = t0 + ty * 4;
        int rr[4];
        #pragma unroll
        for (int i = 0; i < 4; i++) {
            int r = rbase + i;
            rr[i] = (r < rows_pb) ? r : (rows_pb - 1);   // clamp smem reads
        }
        #pragma unroll
        for (int k = 0; k < F; k++) {
            float4 wv = *(const float4*)&Ws[k * F + c0];
            #pragma unroll
            for (int i = 0; i < 4; i++) {
                float yv = h2[rr[i] * 65 + k];
                acc[i][0] += yv * wv.x;
                acc[i][1] += yv * wv.y;
                acc[i][2] += yv * wv.z;
                acc[i][3] += yv * wv.w;
            }
        }
        #pragma unroll
        for (int i = 0; i < 4; i++) {
            int lr = rbase + i;
            int g  = row0 + lr;
            if (lr < rows_pb && g < N) {
                float4 v = make_float4(acc[i][0], acc[i][1], acc[i][2], acc[i][3]);
                *(float4*)(out + g * F + c0) = v;
            }
        }
    }
}

// ---------------------------------------------------------------- launch
extern "C" void kernel_launch(void* const* d_in, const int* in_sizes, int n_in,
                              void* d_out, int out_size) {
    const float* feat = (const float*)d_in[0];
    const int*   src  = (const int*)d_in[1];
    const int*   dst  = (const int*)d_in[2];
    const float* Wm   = (const float*)d_in[3];
    const float* bias = (const float*)d_in[4];
    float* out = (float*)d_out;

    int N = in_sizes[0] / F;   // 100000
    int E = in_sizes[1];       // 1000000

    int dev = 0;
    cudaGetDevice(&dev);
    int smcount = 0;
    cudaDeviceGetAttribute(&smcount, cudaDevAttrMultiProcessorCount, dev);
    if (smcount <= 0) smcount = 148;

    int rows_pb = (N + smcount - 1) / smcount;
    if (rows_pb > ROWS_PB_CAP) rows_pb = ROWS_PB_CAP;
    int nblocks = (N + rows_pb - 1) / rows_pb;        // <= smcount
    if (nblocks > smcount) nblocks = smcount;
    rows_pb = (N + nblocks - 1) / nblocks;
    size_t smem = (size_t)(rows_pb * 65 + F * F) * sizeof(float);
    cudaFuncSetAttribute(k_fused, cudaFuncAttributeMaxDynamicSharedMemorySize,
                         (int)smem);

    int nb_n   = (N + 255) / 256;
    int nb_e   = (E + 255) / 256;
    int nb_sc  = (N + SCAN_BLK - 1) / SCAN_BLK;
    int nb_hop = (N * 32 + 255) / 256;

    k_zero<<<nb_n, 256>>>(N);
    k_hist<<<nb_e, 256>>>(dst, E);
    k_scan1<<<nb_sc, SCAN_BLK>>>(N);
    k_scan2<<<1, 32>>>(nb_sc);
    k_scan3<<<nb_n, 256>>>(N, E);
    k_fill<<<nb_e, 256>>>(src, dst, E);
    k_hop1<<<nb_hop, 256>>>(feat, out, N);
    k_fused<<<nblocks, 1024, smem>>>(out, out, Wm, bias, N, rows_pb, nblocks);
}

// round 8
// speedup vs baseline: 1.0254x; 1.0254x over previous
#include <cuda_runtime.h>
#include <cuda_bf16.h>

// SGConv: out = (D^-1/2 A D^-1/2)^2 * feat @ W + b
// N=100000 nodes, 64 features, E=1000000 edges.
//
// Memory-guard constraints (R1/R3): big __device__ segments trigger a fixed
// 128MiB driver arena inside the checkpoint window; pre-main CUDA calls break
// harness handles (R2). => globals ~5.6MB; h1 lives in d_out; h2 lives in
// shared memory of the persistent fused kernel.
//
// R8 vs R7 (432us REGRESSION): the 4x MLP-batched gather unroll was the
// culprit (documented B300 cross-CTA L1tex-queue contention: spread ~ oe*MLP).
// Reverted to R5's simple gather loop (R5 = 239.6us). Kept: 1024-thread
// k_fused, norm fused into scan1, bounded barrier spin. New: parallel scan2
// (was 8us of serial dependent loads on 1 thread).

#define MAXN 100000
#define MAXE 1000000
#define F 64
#define SCAN_BLK 1024
#define ROWS_PB_CAP 800   // smem: 800*65*4 + 16KB < 227KB opt-in limit

__device__ int   g_deg[MAXN];
__device__ int   g_cur[MAXN];
__device__ int   g_rowptr[MAXN + 1];
__device__ int   g_chunksum[128];
__device__ int   g_chunkoff[128];
__device__ float g_norm[MAXN];
__device__ int   g_csr_src[MAXE];
__device__ int   g_bar;

// ---------------------------------------------------------------- zero
__global__ void k_zero(int N) {
    int i = blockIdx.x * blockDim.x + threadIdx.x;
    if (i < N) { g_deg[i] = 0; g_cur[i] = 0; }
    if (i == 0) g_bar = 0;
}

// ---------------------------------------------------------------- histogram
__global__ void k_hist(const int* __restrict__ dst, int E) {
    int e = blockIdx.x * blockDim.x + threadIdx.x;
    if (e < E) atomicAdd(&g_deg[dst[e]], 1);
}

// ---------------------------------------------------------------- scan (+norm fused)
__global__ void k_scan1(int N) {
    __shared__ int sh[SCAN_BLK];
    int t = threadIdx.x;
    int i = blockIdx.x * SCAN_BLK + t;
    int v = (i < N) ? g_deg[i] : 0;
    if (i < N) g_norm[i] = rsqrtf(fmaxf((float)v, 1.0f));   // fused norm
    sh[t] = v;
    __syncthreads();
    #pragma unroll
    for (int off = 1; off < SCAN_BLK; off <<= 1) {
        int x = (t >= off) ? sh[t - off] : 0;
        __syncthreads();
        sh[t] += x;
        __syncthreads();
    }
    if (i < N) g_rowptr[i] = sh[t] - v;          // exclusive (partial)
    if (t == SCAN_BLK - 1) g_chunksum[blockIdx.x] = sh[t];
}

// parallel exclusive scan of up to 128 chunk sums (was 1-thread serial, 8us)
__global__ void k_scan2(int nblocks) {
    __shared__ int sh[128];
    int t = threadIdx.x;
    int v = (t < nblocks) ? g_chunksum[t] : 0;
    sh[t] = v;
    __syncthreads();
    #pragma unroll
    for (int off = 1; off < 128; off <<= 1) {
        int x = (t >= off) ? sh[t - off] : 0;
        __syncthreads();
        sh[t] += x;
        __syncthreads();
    }
    if (t < nblocks) g_chunkoff[t] = sh[t] - v;   // exclusive
}

__global__ void k_scan3(int N, int E) {
    int i = blockIdx.x * blockDim.x + threadIdx.x;
    if (i < N) g_rowptr[i] += g_chunkoff[i / SCAN_BLK];
    if (i == 0) g_rowptr[N] = E;
}

// ---------------------------------------------------------------- CSR fill
__global__ void k_fill(const int* __restrict__ src, const int* __restrict__ dst, int E) {
    int e = blockIdx.x * blockDim.x + threadIdx.x;
    if (e < E) {
        int d = dst[e];
        int p = g_rowptr[d] + atomicAdd(&g_cur[d], 1);
        g_csr_src[p] = src[e];
    }
}

// ---------------------------------------------------------------- gather core
// one warp per dst row; lane owns float2. SIMPLE loop (R5 form): natural
// scheduling gives MLP~2 without flooding the L1tex wavefront queue.
__device__ __forceinline__ float2 gather_row(const float2* __restrict__ xr,
                                             int beg, int end, float nd, int lane) {
    float2 acc = make_float2(0.f, 0.f);
    for (int j = beg; j < end; j++) {
        int   s = __ldg(&g_csr_src[j]);
        float w = __ldg(&g_norm[s]);
        float2 v = xr[s * 32 + lane];
        acc.x += w * v.x;
        acc.y += w * v.y;
    }
    acc.x *= nd;
    acc.y *= nd;
    return acc;
}

// ---------------------------------------------------------------- hop1
__global__ void k_hop1(const float* __restrict__ x, float* __restrict__ y, int N) {
    int warp = (blockIdx.x * blockDim.x + threadIdx.x) >> 5;
    int lane = threadIdx.x & 31;
    if (warp >= N) return;
    int beg = g_rowptr[warp];
    int end = g_rowptr[warp + 1];
    float nd = g_norm[warp];
    float2 acc = gather_row((const float2*)x, beg, end, nd, lane);
    ((float2*)y)[warp * 32 + lane] = acc;
}

// ---------------------------------------------------------------- fused hop2 + GEMM
// nblocks <= #SMs, big dyn smem forces 1 block/SM -> all blocks resident ->
// grid barrier safe. 1024 threads: 32 gather warps, 2x GEMM issue vs 512.
// smem: h2[rows_pb][65] (padded) then W[64][64]. x and out ALIAS (= d_out);
// phases separated by the grid barrier.
__global__ void __launch_bounds__(1024, 1)
k_fused(const float* x, float* out, const float* __restrict__ Wm,
        const float* __restrict__ bias, int N, int rows_pb, int nblocks) {
    extern __shared__ float sm[];
    float* h2 = sm;                       // rows_pb * 65
    float* Ws = sm + rows_pb * 65;        // 64*64

    int tid  = threadIdx.x;
    int wid  = tid >> 5;
    int lane = tid & 31;
    int row0 = blockIdx.x * rows_pb;

    for (int i = tid; i < F * F; i += blockDim.x) Ws[i] = Wm[i];

    // ---- phase 1: gather h2 rows into smem (reads x = d_out anywhere)
    const float2* xr = (const float2*)x;
    for (int lr = wid; lr < rows_pb; lr += 32) {
        int r = row0 + lr;
        float2 acc = make_float2(0.f, 0.f);
        if (r < N) {
            acc = gather_row(xr, g_rowptr[r], g_rowptr[r + 1], g_norm[r], lane);
        }
        h2[lr * 65 + 2 * lane]     = acc.x;
        h2[lr * 65 + 2 * lane + 1] = acc.y;
    }

    // ---- software grid barrier (all nblocks co-resident by construction).
    // BOUNDED spin: unreachable bound in correct operation; guarantees the
    // kernel can never hang the harness if an invariant is ever violated.
    __syncthreads();
    __threadfence();
    if (tid == 0) {
        atomicAdd(&g_bar, 1);
        long long guard = 0;
        while (*(volatile int*)&g_bar < nblocks && guard < (160LL << 20)) {
            __nanosleep(64);
            guard++;
        }
    }
    __syncthreads();
    __threadfence();

    // ---- phase 2: out rows = h2 @ W + b, 256-row tiles, 4x4 per thread
    int tx = tid & 15;          // 16 col groups * 4 cols = 64
    int ty = tid >> 4;          // 64 row groups * 4 rows = 256 rows/tile
    int c0 = tx * 4;
    float4 bv = *(const float4*)&bias[c0];

    for (int t0 = 0; t0 < rows_pb; t0 += 256) {
        float acc[4][4];
        #pragma unroll
        for (int i = 0; i < 4; i++) {
            acc[i][0] = bv.x; acc[i][1] = bv.y; acc[i][2] = bv.z; acc[i][3] = bv.w;
        }
        int rbase = t0 + ty * 4;
        int rr[4];
        #pragma unroll
        for (int i = 0; i < 4; i++) {
            int r = rbase + i;
            rr[i] = (r < rows_pb) ? r : (rows_pb - 1);   // clamp smem reads
        }
        #pragma unroll
        for (int k = 0; k < F; k++) {
            float4 wv = *(const float4*)&Ws[k * F + c0];
            #pragma unroll
            for (int i = 0; i < 4; i++) {
                float yv = h2[rr[i] * 65 + k];
                acc[i][0] += yv * wv.x;
                acc[i][1] += yv * wv.y;
                acc[i][2] += yv * wv.z;
                acc[i][3] += yv * wv.w;
            }
        }
        #pragma unroll
        for (int i = 0; i < 4; i++) {
            int lr = rbase + i;
            int g  = row0 + lr;
            if (lr < rows_pb && g < N) {
                float4 v = make_float4(acc[i][0], acc[i][1], acc[i][2], acc[i][3]);
                *(float4*)(out + g * F + c0) = v;
            }
        }
    }
}

// ---------------------------------------------------------------- launch
extern "C" void kernel_launch(void* const* d_in, const int* in_sizes, int n_in,
                              void* d_out, int out_size) {
    const float* feat = (const float*)d_in[0];
    const int*   src  = (const int*)d_in[1];
    const int*   dst  = (const int*)d_in[2];
    const float* Wm   = (const float*)d_in[3];
    const float* bias = (const float*)d_in[4];
    float* out = (float*)d_out;

    int N = in_sizes[0] / F;   // 100000
    int E = in_sizes[1];       // 1000000

    int dev = 0;
    cudaGetDevice(&dev);
    int smcount = 0;
    cudaDeviceGetAttribute(&smcount, cudaDevAttrMultiProcessorCount, dev);
    if (smcount <= 0) smcount = 148;

    int rows_pb = (N + smcount - 1) / smcount;
    if (rows_pb > ROWS_PB_CAP) rows_pb = ROWS_PB_CAP;
    int nblocks = (N + rows_pb - 1) / rows_pb;        // <= smcount
    if (nblocks > smcount) nblocks = smcount;
    rows_pb = (N + nblocks - 1) / nblocks;
    size_t smem = (size_t)(rows_pb * 65 + F * F) * sizeof(float);
    cudaFuncSetAttribute(k_fused, cudaFuncAttributeMaxDynamicSharedMemorySize,
                         (int)smem);

    int nb_n   = (N + 255) / 256;
    int nb_e   = (E + 255) / 256;
    int nb_sc  = (N + SCAN_BLK - 1) / SCAN_BLK;
    int nb_hop = (N * 32 + 255) / 256;

    k_zero<<<nb_n, 256>>>(N);
    k_hist<<<nb_e, 256>>>(dst, E);
    k_scan1<<<nb_sc, SCAN_BLK>>>(N);
    k_scan2<<<1, 128>>>(nb_sc);
    k_scan3<<<nb_n, 256>>>(N, E);
    k_fill<<<nb_e, 256>>>(src, dst, E);
    k_hop1<<<nb_hop, 256>>>(feat, out, N);
    k_fused<<<nblocks, 1024, smem>>>(out, out, Wm, bias, N, rows_pb, nblocks);
}

// round 9
// speedup vs baseline: 1.9742x; 1.9252x over previous
#include <cuda_runtime.h>
#include <cuda_bf16.h>

// SGConv: out = (D^-1/2 A D^-1/2)^2 * feat @ W + b
// N=100000 nodes, 64 features, E=1000000 edges.
//
// Memory-guard constraints (R1/R3): big __device__ segments trigger a fixed
// 128MiB driver arena inside the checkpoint window; pre-main CUDA calls break
// harness handles (R2). => globals ~5.6MB; h1 lives in d_out; h2 lives in
// shared memory of the persistent fused kernel.
//
// History: R5 = 239.6us (k_fused 512 thr). R7/R8 = ~425us REGRESSION traced
// to k_fused at 1024 threads: __launch_bounds__(1024,1) caps regs at 64 ->
// GEMM+gather spills to local. R9: k_fused back to 512 threads (128-reg cap),
// keep parallel scan2 + fused norm + bounded spin, and NEW: half-warp-per-row
// float4 gather in the fused phase (32 concurrent rows/SM, half the load
// instructions, no front-batched MLP).

#define MAXN 100000
#define MAXE 1000000
#define F 64
#define SCAN_BLK 1024
// smem: rows_pb*68*4 + 16KB <= ~227KB opt-in  =>  rows_pb <= 783. Cap 760.
#define ROWS_PB_CAP 760
#define H2S 68          // h2 row stride in floats (mult of 4 -> aligned float4)

__device__ int   g_deg[MAXN];
__device__ int   g_cur[MAXN];
__device__ int   g_rowptr[MAXN + 1];
__device__ int   g_chunksum[128];
__device__ int   g_chunkoff[128];
__device__ float g_norm[MAXN];
__device__ int   g_csr_src[MAXE];
__device__ int   g_bar;

// ---------------------------------------------------------------- zero
__global__ void k_zero(int N) {
    int i = blockIdx.x * blockDim.x + threadIdx.x;
    if (i < N) { g_deg[i] = 0; g_cur[i] = 0; }
    if (i == 0) g_bar = 0;
}

// ---------------------------------------------------------------- histogram
__global__ void k_hist(const int* __restrict__ dst, int E) {
    int e = blockIdx.x * blockDim.x + threadIdx.x;
    if (e < E) atomicAdd(&g_deg[dst[e]], 1);
}

// ---------------------------------------------------------------- scan (+norm fused)
__global__ void k_scan1(int N) {
    __shared__ int sh[SCAN_BLK];
    int t = threadIdx.x;
    int i = blockIdx.x * SCAN_BLK + t;
    int v = (i < N) ? g_deg[i] : 0;
    if (i < N) g_norm[i] = rsqrtf(fmaxf((float)v, 1.0f));   // fused norm
    sh[t] = v;
    __syncthreads();
    #pragma unroll
    for (int off = 1; off < SCAN_BLK; off <<= 1) {
        int x = (t >= off) ? sh[t - off] : 0;
        __syncthreads();
        sh[t] += x;
        __syncthreads();
    }
    if (i < N) g_rowptr[i] = sh[t] - v;          // exclusive (partial)
    if (t == SCAN_BLK - 1) g_chunksum[blockIdx.x] = sh[t];
}

// parallel exclusive scan of up to 128 chunk sums
__global__ void k_scan2(int nblocks) {
    __shared__ int sh[128];
    int t = threadIdx.x;
    int v = (t < nblocks) ? g_chunksum[t] : 0;
    sh[t] = v;
    __syncthreads();
    #pragma unroll
    for (int off = 1; off < 128; off <<= 1) {
        int x = (t >= off) ? sh[t - off] : 0;
        __syncthreads();
        sh[t] += x;
        __syncthreads();
    }
    if (t < nblocks) g_chunkoff[t] = sh[t] - v;   // exclusive
}

__global__ void k_scan3(int N, int E) {
    int i = blockIdx.x * blockDim.x + threadIdx.x;
    if (i < N) g_rowptr[i] += g_chunkoff[i / SCAN_BLK];
    if (i == 0) g_rowptr[N] = E;
}

// ---------------------------------------------------------------- CSR fill
__global__ void k_fill(const int* __restrict__ src, const int* __restrict__ dst, int E) {
    int e = blockIdx.x * blockDim.x + threadIdx.x;
    if (e < E) {
        int d = dst[e];
        int p = g_rowptr[d] + atomicAdd(&g_cur[d], 1);
        g_csr_src[p] = src[e];
    }
}

// ---------------------------------------------------------------- hop1
// EXACT R5 form (proven): one warp per dst node; lane owns float2.
__global__ void k_hop1(const float* __restrict__ x, float* __restrict__ y, int N) {
    int warp = (blockIdx.x * blockDim.x + threadIdx.x) >> 5;
    int lane = threadIdx.x & 31;
    if (warp >= N) return;
    int beg = g_rowptr[warp];
    int end = g_rowptr[warp + 1];
    float nd = g_norm[warp];
    float2 acc = make_float2(0.f, 0.f);
    const float2* xr = (const float2*)x;
    for (int j = beg; j < end; j++) {
        int   s = __ldg(&g_csr_src[j]);
        float w = __ldg(&g_norm[s]);
        float2 v = xr[s * 32 + lane];
        acc.x += w * v.x;
        acc.y += w * v.y;
    }
    ((float2*)y)[warp * 32 + lane] = acc;
    // note: nd folded below? keep R5 exact: nd applied inside loop in R5?
    // R5 applied nd per gather_row result; here fold at store:
    // (acc already unscaled) -> scale:
    // (kept simple: see store above) -- we scale before store instead:
}

// Correction: scale-by-nd version (used; the above comment block is inert).
__global__ void k_hop1s(const float* __restrict__ x, float* __restrict__ y, int N) {
    int warp = (blockIdx.x * blockDim.x + threadIdx.x) >> 5;
    int lane = threadIdx.x & 31;
    if (warp >= N) return;
    int beg = g_rowptr[warp];
    int end = g_rowptr[warp + 1];
    float nd = g_norm[warp];
    float2 acc = make_float2(0.f, 0.f);
    const float2* xr = (const float2*)x;
    for (int j = beg; j < end; j++) {
        int   s = __ldg(&g_csr_src[j]);
        float w = __ldg(&g_norm[s]);
        float2 v = xr[s * 32 + lane];
        acc.x += w * v.x;
        acc.y += w * v.y;
    }
    acc.x *= nd;
    acc.y *= nd;
    ((float2*)y)[warp * 32 + lane] = acc;
}

// ---------------------------------------------------------------- fused hop2 + GEMM
// 512 threads (128-reg cap -> no spills). Phase 1: HALF-WARP per row with
// float4 lanes: 16 warps -> 32 concurrent row streams, half the LDG count.
// smem: h2[rows_pb][H2S] then W[64][64]. x and out ALIAS (= d_out); phases
// separated by a software grid barrier (all blocks resident: nblocks<=#SMs,
// 1 block/SM pinned by ~200KB smem).
__global__ void __launch_bounds__(512, 1)
k_fused(const float* x, float* out, const float* __restrict__ Wm,
        const float* __restrict__ bias, int N, int rows_pb, int nblocks) {
    extern __shared__ float sm[];
    float* h2 = sm;                        // rows_pb * H2S
    float* Ws = sm + rows_pb * H2S;        // 64*64

    int tid  = threadIdx.x;
    int wid  = tid >> 5;
    int lane = tid & 31;
    int half = lane >> 4;                  // 0/1: which row of the pair
    int lh   = lane & 15;                  // lane within half-warp
    int row0 = blockIdx.x * rows_pb;

    for (int i = tid; i < F * F; i += blockDim.x) Ws[i] = Wm[i];

    // ---- phase 1: half-warp gathers one row; float4 per lane (16*16B=256B)
    const float4* xf = (const float4*)x;
    for (int lr = (wid << 1) | half; lr < rows_pb; lr += 32) {
        int r = row0 + lr;
        float4 acc = make_float4(0.f, 0.f, 0.f, 0.f);
        if (r < N) {
            int beg = g_rowptr[r];
            int end = g_rowptr[r + 1];
            float nd = g_norm[r];
            for (int j = beg; j < end; j++) {
                int   s = __ldg(&g_csr_src[j]);
                float w = __ldg(&g_norm[s]);
                float4 v = xf[s * 16 + lh];
                acc.x += w * v.x; acc.y += w * v.y;
                acc.z += w * v.z; acc.w += w * v.w;
            }
            acc.x *= nd; acc.y *= nd; acc.z *= nd; acc.w *= nd;
        }
        *(float4*)&h2[lr * H2S + 4 * lh] = acc;   // aligned: H2S%4==0
    }

    // ---- software grid barrier (bounded spin: cannot hang the harness)
    __syncthreads();
    __threadfence();
    if (tid == 0) {
        atomicAdd(&g_bar, 1);
        long long guard = 0;
        while (*(volatile int*)&g_bar < nblocks && guard < (160LL << 20)) {
            __nanosleep(64);
            guard++;
        }
    }
    __syncthreads();
    __threadfence();

    // ---- phase 2: out rows = h2 @ W + b, 128-row tiles, 4x4 per thread
    int tx = tid & 15;          // 16 col groups * 4 cols = 64
    int ty = tid >> 4;          // 32 row groups * 4 rows = 128 rows/tile
    int c0 = tx * 4;
    float4 bv = *(const float4*)&bias[c0];

    for (int t0 = 0; t0 < rows_pb; t0 += 128) {
        float acc[4][4];
        #pragma unroll
        for (int i = 0; i < 4; i++) {
            acc[i][0] = bv.x; acc[i][1] = bv.y; acc[i][2] = bv.z; acc[i][3] = bv.w;
        }
        int rbase = t0 + ty * 4;
        int rr[4];
        #pragma unroll
        for (int i = 0; i < 4; i++) {
            int r = rbase + i;
            rr[i] = (r < rows_pb) ? r : (rows_pb - 1);   // clamp smem reads
        }
        #pragma unroll
        for (int k = 0; k < F; k++) {
            float4 wv = *(const float4*)&Ws[k * F + c0];
            #pragma unroll
            for (int i = 0; i < 4; i++) {
                float yv = h2[rr[i] * H2S + k];
                acc[i][0] += yv * wv.x;
                acc[i][1] += yv * wv.y;
                acc[i][2] += yv * wv.z;
                acc[i][3] += yv * wv.w;
            }
        }
        #pragma unroll
        for (int i = 0; i < 4; i++) {
            int lr = rbase + i;
            int g  = row0 + lr;
            if (lr < rows_pb && g < N) {
                float4 v = make_float4(acc[i][0], acc[i][1], acc[i][2], acc[i][3]);
                *(float4*)(out + g * F + c0) = v;
            }
        }
    }
}

// ---------------------------------------------------------------- launch
extern "C" void kernel_launch(void* const* d_in, const int* in_sizes, int n_in,
                              void* d_out, int out_size) {
    const float* feat = (const float*)d_in[0];
    const int*   src  = (const int*)d_in[1];
    const int*   dst  = (const int*)d_in[2];
    const float* Wm   = (const float*)d_in[3];
    const float* bias = (const float*)d_in[4];
    float* out = (float*)d_out;

    int N = in_sizes[0] / F;   // 100000
    int E = in_sizes[1];       // 1000000

    int dev = 0;
    cudaGetDevice(&dev);
    int smcount = 0;
    cudaDeviceGetAttribute(&smcount, cudaDevAttrMultiProcessorCount, dev);
    if (smcount <= 0) smcount = 148;

    int rows_pb = (N + smcount - 1) / smcount;
    if (rows_pb > ROWS_PB_CAP) rows_pb = ROWS_PB_CAP;
    int nblocks = (N + rows_pb - 1) / rows_pb;        // <= smcount
    if (nblocks > smcount) nblocks = smcount;
    rows_pb = (N + nblocks - 1) / nblocks;
    size_t smem = (size_t)(rows_pb * H2S + F * F) * sizeof(float);
    cudaFuncSetAttribute(k_fused, cudaFuncAttributeMaxDynamicSharedMemorySize,
                         (int)smem);

    int nb_n   = (N + 255) / 256;
    int nb_e   = (E + 255) / 256;
    int nb_sc  = (N + SCAN_BLK - 1) / SCAN_BLK;
    int nb_hop = (N * 32 + 255) / 256;

    k_zero<<<nb_n, 256>>>(N);
    k_hist<<<nb_e, 256>>>(dst, E);
    k_scan1<<<nb_sc, SCAN_BLK>>>(N);
    k_scan2<<<1, 128>>>(nb_sc);
    k_scan3<<<nb_n, 256>>>(N, E);
    k_fill<<<nb_e, 256>>>(src, dst, E);
    k_hop1s<<<nb_hop, 256>>>(feat, out, N);
    k_fused<<<nblocks, 512, smem>>>(out, out, Wm, bias, N, rows_pb, nblocks);
}